// round 4
// baseline (speedup 1.0000x reference)
#include <cuda_runtime.h>
#include <math.h>

// ---------------- problem constants ----------------
#define B_  4
#define Q_  1024
#define D_  1024
#define NH_ 16
#define DH_ 64
#define DI_ 4096
#define M_  (B_*Q_)      // 4096 rows

// ---------------- device scratch (static; no allocations) ----------------
__device__ float g_heads[(size_t)M_*3*D_];           // [b*Q+i, 3D]   48 MB
__device__ float g_rk   [(size_t)Q_*D_];             // [j, n*64+d]    4 MB
__device__ float g_QW   [(size_t)B_*NH_*Q_*DH_];     // [b,n,i,d]     16 MB
__device__ float g_QR   [(size_t)B_*NH_*Q_*DH_];     // 16 MB
__device__ float g_Kp   [(size_t)B_*NH_*Q_*DH_];     // 16 MB
__device__ float g_Vt   [(size_t)B_*NH_*DH_*Q_];     // [b,n,d,j]     16 MB
__device__ float g_rkB  [(size_t)NH_*Q_*DH_];        // [n,j,d]        4 MB
__device__ float g_AC   [(size_t)B_*NH_*Q_*Q_];      // scores/prob  256 MB
__device__ float g_BD   [(size_t)B_*NH_*Q_*Q_];      // BD_raw       256 MB
__device__ float g_av   [(size_t)M_*D_];             // 16 MB
__device__ float g_tmp  [(size_t)M_*D_];             // 16 MB
__device__ float g_out1 [(size_t)M_*D_];             // 16 MB
__device__ float g_ff1  [(size_t)M_*DI_];            // 64 MB

// ---------------- generic tiled SGEMM:  C = A @ B^T ----------------
// A: [M,K] row-major (lda), B: [N,K] row-major (ldb), C: [M,N] (ldc)
// batch offset for operand X computed as (z/16)*xHi + (z%16)*xLo
// mode bits: 1 = +bias[col], 2 = relu, 4 = +resid[cOff + row*ldc + col]
template<int BM,int BN,int BK,int TM,int TN>
__global__ void __launch_bounds__((BM/TM)*(BN/TN))
gemm_k(const float* __restrict__ A, int lda, long aHi, long aLo,
       const float* __restrict__ B, int ldb, long bHi, long bLo,
       float*       __restrict__ C, int ldc, long cHi, long cLo,
       const float* __restrict__ bias,
       const float* __restrict__ resid,
       int K, int mode)
{
    constexpr int NT = (BM/TM)*(BN/TN);
    __shared__ float As[BK][BM+4];
    __shared__ float Bs[BK][BN+4];

    const int z   = blockIdx.z;
    const long aOff = (long)(z/16)*aHi + (long)(z%16)*aLo;
    const long bOff = (long)(z/16)*bHi + (long)(z%16)*bLo;
    const long cOff = (long)(z/16)*cHi + (long)(z%16)*cLo;

    const int m0 = blockIdx.y * BM;
    const int n0 = blockIdx.x * BN;
    const int tid = threadIdx.x;
    const int tx = tid % (BN/TN);
    const int ty = tid / (BN/TN);

    float acc[TM][TN];
#pragma unroll
    for (int i = 0; i < TM; i++)
#pragma unroll
        for (int j = 0; j < TN; j++) acc[i][j] = 0.f;

    const float* Ab = A + aOff + (long)m0 * lda;
    const float* Bb = B + bOff + (long)n0 * ldb;

    for (int k0 = 0; k0 < K; k0 += BK) {
        // load A tile (BM x BK) transposed into smem, float4 loads
#pragma unroll
        for (int idx = tid; idx < BM*BK/4; idx += NT) {
            int m  = idx / (BK/4);
            int kv = idx % (BK/4);
            float4 v = *(const float4*)(Ab + (long)m*lda + k0 + kv*4);
            As[kv*4+0][m] = v.x; As[kv*4+1][m] = v.y;
            As[kv*4+2][m] = v.z; As[kv*4+3][m] = v.w;
        }
#pragma unroll
        for (int idx = tid; idx < BN*BK/4; idx += NT) {
            int n  = idx / (BK/4);
            int kv = idx % (BK/4);
            float4 v = *(const float4*)(Bb + (long)n*ldb + k0 + kv*4);
            Bs[kv*4+0][n] = v.x; Bs[kv*4+1][n] = v.y;
            Bs[kv*4+2][n] = v.z; Bs[kv*4+3][n] = v.w;
        }
        __syncthreads();

#pragma unroll
        for (int kk = 0; kk < BK; kk++) {
            float ar[TM], br[TN];
#pragma unroll
            for (int i = 0; i < TM; i++) ar[i] = As[kk][ty*TM + i];
#pragma unroll
            for (int j = 0; j < TN; j++) br[j] = Bs[kk][tx*TN + j];
#pragma unroll
            for (int i = 0; i < TM; i++)
#pragma unroll
                for (int j = 0; j < TN; j++)
                    acc[i][j] += ar[i]*br[j];
        }
        __syncthreads();
    }

#pragma unroll
    for (int i = 0; i < TM; i++) {
        long row = m0 + ty*TM + i;
#pragma unroll
        for (int j = 0; j < TN; j++) {
            int col = n0 + tx*TN + j;
            float v = acc[i][j];
            if (mode & 1) v += bias[col];
            if (mode & 2) v = fmaxf(v, 0.f);
            if (mode & 4) v += resid[cOff + row*ldc + col];
            C[cOff + row*ldc + col] = v;
        }
    }
}

// ---------------- repack: heads -> QW/QR/Kp/Vt, rk -> rkB ----------------
__global__ void repack_k(const float* __restrict__ rwb, const float* __restrict__ rrb)
{
    long idx = (long)blockIdx.x * blockDim.x + threadIdx.x;   // over B*NH*Q*DH = 4M
    if (idx >= (long)B_*NH_*Q_*DH_) return;
    int d = idx & 63;
    int i = (int)((idx >> 6) & 1023);
    int n = (int)((idx >> 16) & 15);
    int b = (int)(idx >> 20);
    long hb = ((long)(b*Q_ + i))*3072 + n*64 + d;
    float qv = g_heads[hb];
    g_QW[idx] = qv + rwb[n*64 + d];
    g_QR[idx] = qv + rrb[n*64 + d];
    g_Kp[idx] = g_heads[hb + 1024];
    g_Vt[(((long)(b*NH_ + n))*64 + d)*1024 + i] = g_heads[hb + 2048];
    if (b == 0) g_rkB[((long)n*1024 + i)*64 + d] = g_rk[(long)i*1024 + n*64 + d];
}

// ---------------- fused shift + mask + scale + softmax ----------------
// prob (written into g_AC) over j in [0, i]; BD[i,j] = BD_raw[i, j-i+Q-1]
__global__ void __launch_bounds__(256) softmax_k()
{
    const int i = blockIdx.x, n = blockIdx.y, b = blockIdx.z;
    const long rbase = (((long)(b*NH_ + n))*Q_ + i)*Q_;
    const int tid = threadIdx.x;

    float s[4];
    float lm = -1e30f;
#pragma unroll
    for (int t = 0; t < 4; t++) {
        int j = tid + t*256;
        if (j <= i) {
            float v = (g_AC[rbase + j] + g_BD[rbase + (j - i + Q_ - 1)]) * 0.125f;
            s[t] = v;
            lm = fmaxf(lm, v);
        } else s[t] = -1e30f;
    }

    __shared__ float red[256];
    red[tid] = lm; __syncthreads();
    for (int off = 128; off; off >>= 1) {
        if (tid < off) red[tid] = fmaxf(red[tid], red[tid + off]);
        __syncthreads();
    }
    float m = red[0];
    __syncthreads();

    float e[4], ls = 0.f;
#pragma unroll
    for (int t = 0; t < 4; t++) { e[t] = expf(s[t] - m); ls += e[t]; }
    red[tid] = ls; __syncthreads();
    for (int off = 128; off; off >>= 1) {
        if (tid < off) red[tid] += red[tid + off];
        __syncthreads();
    }
    float inv = 1.f / red[0];
#pragma unroll
    for (int t = 0; t < 4; t++)
        g_AC[rbase + tid + t*256] = e[t] * inv;
}

// ---------------- LayerNorm over rows of length D_ ----------------
__global__ void __launch_bounds__(256) ln_k(const float* __restrict__ x,
                                            const float* __restrict__ g,
                                            const float* __restrict__ bb,
                                            float* __restrict__ y)
{
    const int row = blockIdx.x;
    const int tid = threadIdx.x;
    const float* xr = x + (long)row*D_;
    float v[4], s = 0.f, s2 = 0.f;
#pragma unroll
    for (int t = 0; t < 4; t++) {
        v[t] = xr[tid + t*256];
        s += v[t]; s2 += v[t]*v[t];
    }
    __shared__ float r1[256], r2[256];
    r1[tid] = s; r2[tid] = s2; __syncthreads();
    for (int off = 128; off; off >>= 1) {
        if (tid < off) { r1[tid] += r1[tid+off]; r2[tid] += r2[tid+off]; }
        __syncthreads();
    }
    float mean = r1[0] * (1.f/D_);
    float var  = r2[0] * (1.f/D_) - mean*mean;
    float rstd = rsqrtf(var + 1e-5f);
#pragma unroll
    for (int t = 0; t < 4; t++) {
        int c = tid + t*256;
        y[(long)row*D_ + c] = (v[t] - mean)*rstd*g[c] + bb[c];
    }
}

// ---------------- host launch ----------------
static float* symaddr(const void* sym) {
    void* p = nullptr;
    cudaGetSymbolAddress(&p, sym);
    return (float*)p;
}

extern "C" void kernel_launch(void* const* d_in, const int* in_sizes, int n_in,
                              void* d_out, int out_size)
{
    const float* w       = (const float*)d_in[0];
    const float* r       = (const float*)d_in[1];
    // d_in[2] = attention_mask (causal triu) -- implied analytically, unused
    const float* qkv_w   = (const float*)d_in[3];
    const float* r_w     = (const float*)d_in[4];
    const float* o_w     = (const float*)d_in[5];
    const float* r_w_bias= (const float*)d_in[6];
    const float* r_r_bias= (const float*)d_in[7];
    const float* ln1_g   = (const float*)d_in[8];
    const float* ln1_b   = (const float*)d_in[9];
    const float* ff_w1   = (const float*)d_in[10];
    const float* ff_b1   = (const float*)d_in[11];
    const float* ff_w2   = (const float*)d_in[12];
    const float* ff_b2   = (const float*)d_in[13];
    const float* ln2_g   = (const float*)d_in[14];
    const float* ln2_b   = (const float*)d_in[15];
    float* out = (float*)d_out;

    float* heads = symaddr(g_heads);
    float* rk    = symaddr(g_rk);
    float* QW    = symaddr(g_QW);
    float* QR    = symaddr(g_QR);
    float* Kp    = symaddr(g_Kp);
    float* Vt    = symaddr(g_Vt);
    float* rkB   = symaddr(g_rkB);
    float* AC    = symaddr(g_AC);
    float* BD    = symaddr(g_BD);
    float* av    = symaddr(g_av);
    float* tmp   = symaddr(g_tmp);
    float* out1  = symaddr(g_out1);
    float* ff1   = symaddr(g_ff1);

    // 1) heads = w @ qkv_w^T   [4096,3072] k=1024
    gemm_k<128,128,16,8,8><<<dim3(3072/128, 4096/128, 1), 256>>>(
        w, 1024, 0,0,  qkv_w, 1024, 0,0,  heads, 3072, 0,0,
        nullptr, nullptr, 1024, 0);

    // 2) rk = r @ r_w^T   [1024,1024] k=1024
    gemm_k<128,128,16,8,8><<<dim3(1024/128, 1024/128, 1), 256>>>(
        r, 1024, 0,0,  r_w, 1024, 0,0,  rk, 1024, 0,0,
        nullptr, nullptr, 1024, 0);

    // 3) repack to per-head layouts (+ bias add for QW/QR)
    repack_k<<<(B_*NH_*Q_*DH_)/256, 256>>>(r_w_bias, r_r_bias);

    // 4) AC[b,n] = QW @ Kp^T   batched 64x [1024,1024] k=64
    gemm_k<128,128,16,8,8><<<dim3(8, 8, 64), 256>>>(
        QW, 64, (long)16*65536, 65536,
        Kp, 64, (long)16*65536, 65536,
        AC, 1024, (long)16*1048576, 1048576,
        nullptr, nullptr, 64, 0);

    // 5) BD_raw[b,n] = QR @ rkB[n]^T   batched (B shared across b)
    gemm_k<128,128,16,8,8><<<dim3(8, 8, 64), 256>>>(
        QR, 64, (long)16*65536, 65536,
        rkB, 64, 0, 65536,
        BD, 1024, (long)16*1048576, 1048576,
        nullptr, nullptr, 64, 0);

    // 6) shift + mask + scale + softmax -> prob in g_AC
    softmax_k<<<dim3(1024, 16, 4), 256>>>();

    // 7) av[b,n] = prob @ Vt^T   batched 64x [1024,64] k=1024
    gemm_k<64,64,16,4,4><<<dim3(1, 16, 64), 256>>>(
        AC, 1024, (long)16*1048576, 1048576,
        Vt, 1024, (long)16*65536, 65536,
        av, 1024, (long)1048576, 64,
        nullptr, nullptr, 1024, 0);

    // 8) tmp = av @ o_w^T + w (residual)
    gemm_k<128,128,16,8,8><<<dim3(8, 32, 1), 256>>>(
        av, 1024, 0,0,  o_w, 1024, 0,0,  tmp, 1024, 0,0,
        nullptr, w, 1024, 4);

    // 9) out1 = LN1(tmp)
    ln_k<<<M_, 256>>>(tmp, ln1_g, ln1_b, out1);

    // 10) ff1 = relu(out1 @ ff_w1^T + b1)   [4096,4096] k=1024
    gemm_k<128,128,16,8,8><<<dim3(32, 32, 1), 256>>>(
        out1, 1024, 0,0,  ff_w1, 1024, 0,0,  ff1, 4096, 0,0,
        ff_b1, nullptr, 1024, 1|2);

    // 11) tmp = ff1 @ ff_w2^T + b2 + out1   [4096,1024] k=4096
    gemm_k<128,128,16,8,8><<<dim3(8, 32, 1), 256>>>(
        ff1, 4096, 0,0,  ff_w2, 4096, 0,0,  tmp, 1024, 0,0,
        ff_b2, out1, 4096, 1|4);

    // 12) out = LN2(tmp)
    ln_k<<<M_, 256>>>(tmp, ln2_g, ln2_b, out);
}

// round 5
// speedup vs baseline: 1.6248x; 1.6248x over previous
#include <cuda_runtime.h>
#include <math.h>

// ---------------- problem constants ----------------
#define B_  4
#define Q_  1024
#define D_  1024
#define NH_ 16
#define DH_ 64
#define DI_ 4096
#define M_  (B_*Q_)      // 4096 rows

// ---------------- device scratch (static; no allocations) ----------------
__device__ float g_heads[(size_t)M_*3*D_];           // [b*Q+i, 3D]   48 MB
__device__ float g_rk   [(size_t)Q_*D_];             // [j, n*64+d]    4 MB
__device__ float g_QW   [(size_t)B_*NH_*Q_*DH_];     // [b,n,i,d]     16 MB
__device__ float g_QR   [(size_t)B_*NH_*Q_*DH_];     // 16 MB
__device__ float g_Kp   [(size_t)B_*NH_*Q_*DH_];     // 16 MB
__device__ float g_Vt   [(size_t)B_*NH_*DH_*Q_];     // [b,n,d,j]     16 MB
__device__ float g_rkB  [(size_t)NH_*Q_*DH_];        // [n,j,d]        4 MB
__device__ float g_AC   [(size_t)B_*NH_*Q_*Q_];      // scores/prob  256 MB
__device__ float g_BD   [(size_t)B_*NH_*Q_*Q_];      // BD_raw       256 MB
__device__ float g_av   [(size_t)M_*D_];             // 16 MB
__device__ float g_tmp  [(size_t)M_*D_];             // 16 MB
__device__ float g_out1 [(size_t)M_*D_];             // 16 MB
__device__ float g_ff1  [(size_t)M_*DI_];            // 64 MB

// ---------------- tf32 helpers ----------------
__device__ __forceinline__ unsigned f2tf32(float f) {
    unsigned u;
    asm("cvt.rna.tf32.f32 %0, %1;" : "=r"(u) : "f"(f));
    return u;
}

__device__ __forceinline__ void mma8(float* d, const unsigned* a, const unsigned* b) {
    asm volatile(
        "mma.sync.aligned.m16n8k8.row.col.f32.tf32.tf32.f32 "
        "{%0,%1,%2,%3}, {%4,%5,%6,%7}, {%8,%9}, {%0,%1,%2,%3};"
        : "+f"(d[0]), "+f"(d[1]), "+f"(d[2]), "+f"(d[3])
        : "r"(a[0]), "r"(a[1]), "r"(a[2]), "r"(a[3]),
          "r"(b[0]), "r"(b[1]));
}

// ---------------- tensor-core tiled GEMM:  C = A @ B^T (tf32 in, fp32 acc) ----
// A: [M,K] row-major (lda), B: [N,K] row-major (ldb), C: [M,N] (ldc)
// batch offset for operand X computed as (z/16)*xHi + (z%16)*xLo
// mode bits: 1 = +bias[col], 2 = relu, 4 = +resid[cOff + row*ldc + col]
// 256 threads = 8 warps arranged (BM/WM) x (BN/WN); (BM/WM)*(BN/WN) must be 8.
template<int BM,int BN,int BK,int WM,int WN>
__global__ void __launch_bounds__(256)
gemm_tc(const float* __restrict__ A, int lda, long aHi, long aLo,
        const float* __restrict__ B, int ldb, long bHi, long bLo,
        float*       __restrict__ C, int ldc, long cHi, long cLo,
        const float* __restrict__ bias,
        const float* __restrict__ resid,
        int K, int mode)
{
    constexpr int MS = WM/16;          // m16 subtiles per warp
    constexpr int NS = WN/8;           // n8 subtiles per warp
    constexpr int WROWS = BM/WM;
    static_assert((BM/WM)*(BN/WN) == 8, "8 warps");

    __shared__ unsigned As[BK][BM+4];
    __shared__ unsigned Bs[BK][BN+4];

    const int z    = blockIdx.z;
    const long aOff = (long)(z/16)*aHi + (long)(z%16)*aLo;
    const long bOff = (long)(z/16)*bHi + (long)(z%16)*bLo;
    const long cOff = (long)(z/16)*cHi + (long)(z%16)*cLo;

    const int m0 = blockIdx.y * BM;
    const int n0 = blockIdx.x * BN;
    const int tid  = threadIdx.x;
    const int wid  = tid >> 5;
    const int lane = tid & 31;
    const int wm = (wid % WROWS) * WM;
    const int wn = (wid / WROWS) * WN;
    const int grp = lane >> 2;   // 0..7
    const int qid = lane & 3;    // 0..3

    float acc[MS][NS][4];
#pragma unroll
    for (int i = 0; i < MS; i++)
#pragma unroll
        for (int j = 0; j < NS; j++)
#pragma unroll
            for (int c = 0; c < 4; c++) acc[i][j][c] = 0.f;

    const float* Ab = A + aOff + (long)m0 * lda;
    const float* Bb = B + bOff + (long)n0 * ldb;

    for (int k0 = 0; k0 < K; k0 += BK) {
        // load A tile (BM x BK), convert to tf32, store transposed [k][m]
#pragma unroll
        for (int idx = tid; idx < BM*BK/4; idx += 256) {
            int m  = idx / (BK/4);
            int kv = idx % (BK/4);
            float4 v = *(const float4*)(Ab + (long)m*lda + k0 + kv*4);
            As[kv*4+0][m] = f2tf32(v.x); As[kv*4+1][m] = f2tf32(v.y);
            As[kv*4+2][m] = f2tf32(v.z); As[kv*4+3][m] = f2tf32(v.w);
        }
#pragma unroll
        for (int idx = tid; idx < BN*BK/4; idx += 256) {
            int n  = idx / (BK/4);
            int kv = idx % (BK/4);
            float4 v = *(const float4*)(Bb + (long)n*ldb + k0 + kv*4);
            Bs[kv*4+0][n] = f2tf32(v.x); Bs[kv*4+1][n] = f2tf32(v.y);
            Bs[kv*4+2][n] = f2tf32(v.z); Bs[kv*4+3][n] = f2tf32(v.w);
        }
        __syncthreads();

#pragma unroll
        for (int ks = 0; ks < BK; ks += 8) {
            unsigned a[MS][4], b[NS][2];
#pragma unroll
            for (int ms = 0; ms < MS; ms++) {
                int m = wm + ms*16 + grp;
                a[ms][0] = As[ks+qid  ][m];
                a[ms][1] = As[ks+qid  ][m+8];
                a[ms][2] = As[ks+qid+4][m];
                a[ms][3] = As[ks+qid+4][m+8];
            }
#pragma unroll
            for (int ns = 0; ns < NS; ns++) {
                int n = wn + ns*8 + grp;
                b[ns][0] = Bs[ks+qid  ][n];
                b[ns][1] = Bs[ks+qid+4][n];
            }
#pragma unroll
            for (int ms = 0; ms < MS; ms++)
#pragma unroll
                for (int ns = 0; ns < NS; ns++)
                    mma8(acc[ms][ns], a[ms], b[ns]);
        }
        __syncthreads();
    }

    // epilogue
#pragma unroll
    for (int ms = 0; ms < MS; ms++) {
#pragma unroll
        for (int ns = 0; ns < NS; ns++) {
#pragma unroll
            for (int half = 0; half < 2; half++) {
                long row = m0 + wm + ms*16 + grp + half*8;
                int  col = n0 + wn + ns*8 + 2*qid;
                float v0 = acc[ms][ns][half*2 + 0];
                float v1 = acc[ms][ns][half*2 + 1];
                if (mode & 1) { v0 += bias[col]; v1 += bias[col+1]; }
                if (mode & 2) { v0 = fmaxf(v0, 0.f); v1 = fmaxf(v1, 0.f); }
                long cbase = cOff + row*ldc + col;
                if (mode & 4) { v0 += resid[cbase]; v1 += resid[cbase+1]; }
                C[cbase]   = v0;
                C[cbase+1] = v1;
            }
        }
    }
}

// ---------------- repack: heads -> QW/QR/Kp/Vt, rk -> rkB ----------------
__global__ void repack_k(const float* __restrict__ rwb, const float* __restrict__ rrb)
{
    long idx = (long)blockIdx.x * blockDim.x + threadIdx.x;   // over B*NH*Q*DH = 4M
    if (idx >= (long)B_*NH_*Q_*DH_) return;
    int d = idx & 63;
    int i = (int)((idx >> 6) & 1023);
    int n = (int)((idx >> 16) & 15);
    int b = (int)(idx >> 20);
    long hb = ((long)(b*Q_ + i))*3072 + n*64 + d;
    float qv = g_heads[hb];
    g_QW[idx] = qv + rwb[n*64 + d];
    g_QR[idx] = qv + rrb[n*64 + d];
    g_Kp[idx] = g_heads[hb + 1024];
    g_Vt[(((long)(b*NH_ + n))*64 + d)*1024 + i] = g_heads[hb + 2048];
    if (b == 0) g_rkB[((long)n*1024 + i)*64 + d] = g_rk[(long)i*1024 + n*64 + d];
}

// ---------------- fused shift + mask + scale + softmax ----------------
// prob (written into g_AC) over j in [0, i]; BD[i,j] = BD_raw[i, j-i+Q-1]
__global__ void __launch_bounds__(256) softmax_k()
{
    const int i = blockIdx.x, n = blockIdx.y, b = blockIdx.z;
    const long rbase = (((long)(b*NH_ + n))*Q_ + i)*Q_;
    const int tid = threadIdx.x;

    float s[4];
    float lm = -1e30f;
#pragma unroll
    for (int t = 0; t < 4; t++) {
        int j = tid + t*256;
        if (j <= i) {
            float v = (g_AC[rbase + j] + g_BD[rbase + (j - i + Q_ - 1)]) * 0.125f;
            s[t] = v;
            lm = fmaxf(lm, v);
        } else s[t] = -1e30f;
    }

    __shared__ float red[256];
    red[tid] = lm; __syncthreads();
    for (int off = 128; off; off >>= 1) {
        if (tid < off) red[tid] = fmaxf(red[tid], red[tid + off]);
        __syncthreads();
    }
    float m = red[0];
    __syncthreads();

    float e[4], ls = 0.f;
#pragma unroll
    for (int t = 0; t < 4; t++) { e[t] = expf(s[t] - m); ls += e[t]; }
    red[tid] = ls; __syncthreads();
    for (int off = 128; off; off >>= 1) {
        if (tid < off) red[tid] += red[tid + off];
        __syncthreads();
    }
    float inv = 1.f / red[0];
#pragma unroll
    for (int t = 0; t < 4; t++)
        g_AC[rbase + tid + t*256] = e[t] * inv;
}

// ---------------- LayerNorm over rows of length D_ ----------------
__global__ void __launch_bounds__(256) ln_k(const float* __restrict__ x,
                                            const float* __restrict__ g,
                                            const float* __restrict__ bb,
                                            float* __restrict__ y)
{
    const int row = blockIdx.x;
    const int tid = threadIdx.x;
    const float* xr = x + (long)row*D_;
    float v[4], s = 0.f, s2 = 0.f;
#pragma unroll
    for (int t = 0; t < 4; t++) {
        v[t] = xr[tid + t*256];
        s += v[t]; s2 += v[t]*v[t];
    }
    __shared__ float r1[256], r2[256];
    r1[tid] = s; r2[tid] = s2; __syncthreads();
    for (int off = 128; off; off >>= 1) {
        if (tid < off) { r1[tid] += r1[tid+off]; r2[tid] += r2[tid+off]; }
        __syncthreads();
    }
    float mean = r1[0] * (1.f/D_);
    float var  = r2[0] * (1.f/D_) - mean*mean;
    float rstd = rsqrtf(var + 1e-5f);
#pragma unroll
    for (int t = 0; t < 4; t++) {
        int c = tid + t*256;
        y[(long)row*D_ + c] = (v[t] - mean)*rstd*g[c] + bb[c];
    }
}

// ---------------- host launch ----------------
static float* symaddr(const void* sym) {
    void* p = nullptr;
    cudaGetSymbolAddress(&p, sym);
    return (float*)p;
}

extern "C" void kernel_launch(void* const* d_in, const int* in_sizes, int n_in,
                              void* d_out, int out_size)
{
    const float* w       = (const float*)d_in[0];
    const float* r       = (const float*)d_in[1];
    // d_in[2] = attention_mask (causal triu) -- implied analytically, unused
    const float* qkv_w   = (const float*)d_in[3];
    const float* r_w     = (const float*)d_in[4];
    const float* o_w     = (const float*)d_in[5];
    const float* r_w_bias= (const float*)d_in[6];
    const float* r_r_bias= (const float*)d_in[7];
    const float* ln1_g   = (const float*)d_in[8];
    const float* ln1_b   = (const float*)d_in[9];
    const float* ff_w1   = (const float*)d_in[10];
    const float* ff_b1   = (const float*)d_in[11];
    const float* ff_w2   = (const float*)d_in[12];
    const float* ff_b2   = (const float*)d_in[13];
    const float* ln2_g   = (const float*)d_in[14];
    const float* ln2_b   = (const float*)d_in[15];
    float* out = (float*)d_out;

    float* heads = symaddr(g_heads);
    float* rk    = symaddr(g_rk);
    float* QW    = symaddr(g_QW);
    float* QR    = symaddr(g_QR);
    float* Kp    = symaddr(g_Kp);
    float* Vt    = symaddr(g_Vt);
    float* rkB   = symaddr(g_rkB);
    float* AC    = symaddr(g_AC);
    float* BD    = symaddr(g_BD);
    float* av    = symaddr(g_av);
    float* tmp   = symaddr(g_tmp);
    float* out1  = symaddr(g_out1);
    float* ff1   = symaddr(g_ff1);

    // 1) heads = w @ qkv_w^T   [4096,3072] k=1024
    gemm_tc<128,128,32,64,32><<<dim3(3072/128, 4096/128, 1), 256>>>(
        w, 1024, 0,0,  qkv_w, 1024, 0,0,  heads, 3072, 0,0,
        nullptr, nullptr, 1024, 0);

    // 2) rk = r @ r_w^T   [1024,1024] k=1024
    gemm_tc<128,128,32,64,32><<<dim3(1024/128, 1024/128, 1), 256>>>(
        r, 1024, 0,0,  r_w, 1024, 0,0,  rk, 1024, 0,0,
        nullptr, nullptr, 1024, 0);

    // 3) repack to per-head layouts (+ bias add for QW/QR)
    repack_k<<<(B_*NH_*Q_*DH_)/256, 256>>>(r_w_bias, r_r_bias);

    // 4) AC[b,n] = QW @ Kp^T   batched 64x [1024,1024] k=64
    gemm_tc<128,128,32,64,32><<<dim3(8, 8, 64), 256>>>(
        QW, 64, (long)16*65536, 65536,
        Kp, 64, (long)16*65536, 65536,
        AC, 1024, (long)16*1048576, 1048576,
        nullptr, nullptr, 64, 0);

    // 5) BD_raw[b,n] = QR @ rkB[n]^T   batched (rk shared across b)
    gemm_tc<128,128,32,64,32><<<dim3(8, 8, 64), 256>>>(
        QR, 64, (long)16*65536, 65536,
        rkB, 64, 0, 65536,
        BD, 1024, (long)16*1048576, 1048576,
        nullptr, nullptr, 64, 0);

    // 6) shift + mask + scale + softmax -> prob in g_AC
    softmax_k<<<dim3(1024, 16, 4), 256>>>();

    // 7) av[b,n] = prob @ Vt^T   batched 64x [1024,64] k=1024
    gemm_tc<128,64,32,32,32><<<dim3(1, 8, 64), 256>>>(
        AC, 1024, (long)16*1048576, 1048576,
        Vt, 1024, (long)16*65536, 65536,
        av, 1024, (long)1048576, 64,
        nullptr, nullptr, 1024, 0);

    // 8) tmp = av @ o_w^T + w (residual)
    gemm_tc<128,128,32,64,32><<<dim3(8, 32, 1), 256>>>(
        av, 1024, 0,0,  o_w, 1024, 0,0,  tmp, 1024, 0,0,
        nullptr, w, 1024, 4);

    // 9) out1 = LN1(tmp)
    ln_k<<<M_, 256>>>(tmp, ln1_g, ln1_b, out1);

    // 10) ff1 = relu(out1 @ ff_w1^T + b1)   [4096,4096] k=1024
    gemm_tc<128,128,32,64,32><<<dim3(32, 32, 1), 256>>>(
        out1, 1024, 0,0,  ff_w1, 1024, 0,0,  ff1, 4096, 0,0,
        ff_b1, nullptr, 1024, 1|2);

    // 11) tmp = ff1 @ ff_w2^T + b2 + out1   [4096,1024] k=4096
    gemm_tc<128,128,32,64,32><<<dim3(8, 32, 1), 256>>>(
        ff1, 4096, 0,0,  ff_w2, 4096, 0,0,  tmp, 1024, 0,0,
        ff_b2, out1, 4096, 1|4);

    // 12) out = LN2(tmp)
    ln_k<<<M_, 256>>>(tmp, ln2_g, ln2_b, out);
}

// round 7
// speedup vs baseline: 2.3159x; 1.4253x over previous
#include <cuda_runtime.h>
#include <math.h>

// ---------------- problem constants ----------------
#define B_  4
#define Q_  1024
#define D_  1024
#define NH_ 16
#define DH_ 64
#define DI_ 4096
#define M_  (B_*Q_)      // 4096 rows

// ---------------- device scratch (static; no allocations) ----------------
__device__ float g_heads[(size_t)M_*3*D_];            // [b*Q+i, 3D]   48 MB
__device__ float g_rk   [(size_t)Q_*D_];              // [j, n*64+d]    4 MB
__device__ float g_rkB  [(size_t)NH_*1152*DH_];       // [n,c,d] pad rows 1024..1151 = 0
__device__ float g_biasK[(size_t)B_*NH_*Q_];          // rwb . k[b,n,j]
__device__ float g_biasR[(size_t)NH_*1152];           // rrb . rk[n,c]   (pad 0)
__device__ float g_av   [(size_t)M_*D_];              // 16 MB
__device__ float g_tmp  [(size_t)M_*D_];              // 16 MB
__device__ float g_out1 [(size_t)M_*D_];              // 16 MB
__device__ float g_ff1  [(size_t)M_*DI_];             // 64 MB

// ---------------- tf32 helpers ----------------
__device__ __forceinline__ unsigned f2tf32(float f) {
    unsigned u;
    asm("cvt.rna.tf32.f32 %0, %1;" : "=r"(u) : "f"(f));
    return u;
}
__device__ __forceinline__ float f2tf32f(float f) { return __uint_as_float(f2tf32(f)); }

__device__ __forceinline__ void mma8(float* d, const unsigned* a, const unsigned* b) {
    asm volatile(
        "mma.sync.aligned.m16n8k8.row.col.f32.tf32.tf32.f32 "
        "{%0,%1,%2,%3}, {%4,%5,%6,%7}, {%8,%9}, {%0,%1,%2,%3};"
        : "+f"(d[0]), "+f"(d[1]), "+f"(d[2]), "+f"(d[3])
        : "r"(a[0]), "r"(a[1]), "r"(a[2]), "r"(a[3]),
          "r"(b[0]), "r"(b[1]));
}

// ---------------- tensor-core tiled GEMM:  C = A @ B^T (tf32 in, fp32 acc) ----
// mode bits: 1 = +bias[col], 2 = relu, 4 = +resid
template<int BM,int BN,int BK,int WM,int WN>
__global__ void __launch_bounds__(256, 2)
gemm_tc(const float* __restrict__ A, int lda, long aHi, long aLo,
        const float* __restrict__ B, int ldb, long bHi, long bLo,
        float*       __restrict__ C, int ldc, long cHi, long cLo,
        const float* __restrict__ bias,
        const float* __restrict__ resid,
        int K, int mode)
{
    constexpr int MS = WM/16;
    constexpr int NS = WN/8;
    constexpr int WROWS = BM/WM;
    static_assert((BM/WM)*(BN/WN) == 8, "8 warps");

    __shared__ unsigned As[BK][BM+4];
    __shared__ unsigned Bs[BK][BN+4];

    const int z    = blockIdx.z;
    const long aOff = (long)(z/16)*aHi + (long)(z%16)*aLo;
    const long bOff = (long)(z/16)*bHi + (long)(z%16)*bLo;
    const long cOff = (long)(z/16)*cHi + (long)(z%16)*cLo;

    const int m0 = blockIdx.y * BM;
    const int n0 = blockIdx.x * BN;
    const int tid  = threadIdx.x;
    const int wid  = tid >> 5;
    const int lane = tid & 31;
    const int wm = (wid % WROWS) * WM;
    const int wn = (wid / WROWS) * WN;
    const int grp = lane >> 2;
    const int qid = lane & 3;

    float acc[MS][NS][4];
#pragma unroll
    for (int i = 0; i < MS; i++)
#pragma unroll
        for (int j = 0; j < NS; j++)
#pragma unroll
            for (int c = 0; c < 4; c++) acc[i][j][c] = 0.f;

    const float* Ab = A + aOff + (long)m0 * lda;
    const float* Bb = B + bOff + (long)n0 * ldb;

    for (int k0 = 0; k0 < K; k0 += BK) {
#pragma unroll
        for (int idx = tid; idx < BM*BK/4; idx += 256) {
            int m  = idx / (BK/4);
            int kv = idx % (BK/4);
            float4 v = *(const float4*)(Ab + (long)m*lda + k0 + kv*4);
            As[kv*4+0][m] = f2tf32(v.x); As[kv*4+1][m] = f2tf32(v.y);
            As[kv*4+2][m] = f2tf32(v.z); As[kv*4+3][m] = f2tf32(v.w);
        }
#pragma unroll
        for (int idx = tid; idx < BN*BK/4; idx += 256) {
            int n  = idx / (BK/4);
            int kv = idx % (BK/4);
            float4 v = *(const float4*)(Bb + (long)n*ldb + k0 + kv*4);
            Bs[kv*4+0][n] = f2tf32(v.x); Bs[kv*4+1][n] = f2tf32(v.y);
            Bs[kv*4+2][n] = f2tf32(v.z); Bs[kv*4+3][n] = f2tf32(v.w);
        }
        __syncthreads();

#pragma unroll
        for (int ks = 0; ks < BK; ks += 8) {
            unsigned a[MS][4], b[NS][2];
#pragma unroll
            for (int ms = 0; ms < MS; ms++) {
                int m = wm + ms*16 + grp;
                a[ms][0] = As[ks+qid  ][m];
                a[ms][1] = As[ks+qid  ][m+8];
                a[ms][2] = As[ks+qid+4][m];
                a[ms][3] = As[ks+qid+4][m+8];
            }
#pragma unroll
            for (int ns = 0; ns < NS; ns++) {
                int n = wn + ns*8 + grp;
                b[ns][0] = Bs[ks+qid  ][n];
                b[ns][1] = Bs[ks+qid+4][n];
            }
#pragma unroll
            for (int ms = 0; ms < MS; ms++)
#pragma unroll
                for (int ns = 0; ns < NS; ns++)
                    mma8(acc[ms][ns], a[ms], b[ns]);
        }
        __syncthreads();
    }

#pragma unroll
    for (int ms = 0; ms < MS; ms++) {
#pragma unroll
        for (int ns = 0; ns < NS; ns++) {
#pragma unroll
            for (int half = 0; half < 2; half++) {
                long row = m0 + wm + ms*16 + grp + half*8;
                int  col = n0 + wn + ns*8 + 2*qid;
                float v0 = acc[ms][ns][half*2 + 0];
                float v1 = acc[ms][ns][half*2 + 1];
                if (mode & 1) { v0 += bias[col]; v1 += bias[col+1]; }
                if (mode & 2) { v0 = fmaxf(v0, 0.f); v1 = fmaxf(v1, 0.f); }
                long cbase = cOff + row*ldc + col;
                if (mode & 4) { v0 += resid[cbase]; v1 += resid[cbase+1]; }
                C[cbase]   = v0;
                C[cbase+1] = v1;
            }
        }
    }
}

// ---------------- prep: bias_k[b,n,j] = rwb[n] . K[b,n,j] ----------------
__global__ void prep_biasK(const float* __restrict__ rwb)
{
    int idx = blockIdx.x*256 + threadIdx.x;     // (b*16+n)*1024 + j
    int j = idx & 1023; int n = (idx >> 10) & 15; int b = idx >> 14;
    const float* kk = g_heads + ((long)(b*1024 + j))*3072 + 1024 + n*64;
    const float* wv = rwb + n*64;
    float s = 0.f;
#pragma unroll
    for (int d = 0; d < 64; d++) s += wv[d]*kk[d];
    g_biasK[idx] = s;
}

// ---------------- prep: rkB[n,c,d] + bias_r[n,c] ----------------
__global__ void prep_rk(const float* __restrict__ rrb)
{
    int idx = blockIdx.x*256 + threadIdx.x;     // n*1024 + c
    int c = idx & 1023; int n = idx >> 10;
    const float* src = g_rk + (long)c*1024 + n*64;
    const float* wv  = rrb + n*64;
    float* dst = g_rkB + ((long)n*1152 + c)*64;
    float s = 0.f;
#pragma unroll
    for (int d = 0; d < 64; d++) { float v = src[d]; dst[d] = v; s += wv[d]*v; }
    g_biasR[n*1152 + c] = s;
}

// ---------------- fused flash attention (AC + banded BD + softmax + AV) ----
// grid (8 i-tiles, 16 heads, 4 batch); 256 threads = 8 warps, warp w owns
// rows [w*16, w*16+16) of the 128-row Q tile. tf32 MMA throughout.
//
// smem (floats), stride 72 rows for MMA operands (conflict-free 8grp+qid):
//   q_s   [128][72]  @ 0       (9216)
//   rA    [256][72]  @ 9216    (18432)  -- rk window; later Ks[128][72] + Vs[128][72]
//   BDs   8 x [16][148] @ 27648 (18944) -- per-warp BD band; overlaid by Ps [16][132]
//   bks   [128] @ 46592
//   brs   [256] @ 46720
// total 46976 floats = 187904 B (dynamic)
#define FL_SMEM_FLOATS 46976

__global__ void __launch_bounds__(256)
flash_k()
{
    extern __shared__ float sm[];
    float* q_s = sm;                 // [128][72]
    float* rA  = sm + 9216;          // rks [256][72]
    float* Ks  = rA;                 // [128][72]
    float* Vs  = rA + 9216;          // [128][72]
    float* BDb = sm + 27648;         // 8 * 2368
    float* bks = sm + 46592;
    float* brs = sm + 46720;

    const int it = blockIdx.x, n = blockIdx.y, b = blockIdx.z;
    const int i0 = it * 128;
    const int tid = threadIdx.x, wid = tid >> 5, lane = tid & 31;
    const int grp = lane >> 2, qid = lane & 3;
    const int r0 = wid * 16;
    const int off_w = 112 - r0;
    float* BDw = BDb + wid*2368;     // warp-private: BD band [16][148] / P [16][132]

    // load q tile (fp32 -> tf32)
    for (int p = tid; p < 128*16; p += 256) {
        int row = p >> 4, f4 = p & 15;
        float4 v = *(const float4*)(g_heads + ((long)(b*1024 + i0 + row))*3072 + n*64 + f4*4);
        float* dst = q_s + row*72 + f4*4;
        dst[0]=f2tf32f(v.x); dst[1]=f2tf32f(v.y); dst[2]=f2tf32f(v.z); dst[3]=f2tf32f(v.w);
    }

    float o[8][4];
#pragma unroll
    for (int ns = 0; ns < 8; ns++)
#pragma unroll
        for (int c = 0; c < 4; c++) o[ns][c] = 0.f;
    float m_r[2] = {-INFINITY, -INFINITY};
    float l_r[2] = {0.f, 0.f};

    for (int J0 = 0; J0 <= i0; J0 += 128) {
        const int W0 = J0 - i0 + 896;          // rk window start (>= 0)

        // ---- load rk window [256][64] ----
        __syncthreads();                        // protect Vs of previous iter
        for (int p = tid; p < 256*16; p += 256) {
            int row = p >> 4, f4 = p & 15;
            float4 v = *(const float4*)(g_rkB + ((long)n*1152 + W0 + row)*64 + f4*4);
            float* dst = rA + row*72 + f4*4;
            dst[0]=f2tf32f(v.x); dst[1]=f2tf32f(v.y); dst[2]=f2tf32f(v.z); dst[3]=f2tf32f(v.w);
        }
        __syncthreads();

        // ---- BD band: warp-local 16 x 144 GEMM, K=64 ----
        {
            float bd[18][4];
#pragma unroll
            for (int ns = 0; ns < 18; ns++)
#pragma unroll
                for (int c = 0; c < 4; c++) bd[ns][c] = 0.f;
#pragma unroll
            for (int ks = 0; ks < 64; ks += 8) {
                unsigned a[4];
                a[0] = __float_as_uint(q_s[(r0+grp  )*72 + ks+qid  ]);
                a[1] = __float_as_uint(q_s[(r0+grp+8)*72 + ks+qid  ]);
                a[2] = __float_as_uint(q_s[(r0+grp  )*72 + ks+qid+4]);
                a[3] = __float_as_uint(q_s[(r0+grp+8)*72 + ks+qid+4]);
#pragma unroll
                for (int ns = 0; ns < 18; ns++) {
                    unsigned bb[2];
                    int rrow = off_w + ns*8 + grp;
                    bb[0] = __float_as_uint(rA[rrow*72 + ks+qid  ]);
                    bb[1] = __float_as_uint(rA[rrow*72 + ks+qid+4]);
                    mma8(bd[ns], a, bb);
                }
            }
#pragma unroll
            for (int ns = 0; ns < 18; ns++) {
                int cw = ns*8 + 2*qid;
                BDw[ grp   *148 + cw] = bd[ns][0]; BDw[ grp   *148 + cw+1] = bd[ns][1];
                BDw[(grp+8)*148 + cw] = bd[ns][2]; BDw[(grp+8)*148 + cw+1] = bd[ns][3];
            }
        }
        __syncthreads();

        // ---- load K, V tiles + bias windows (overwrites rk window) ----
        for (int p = tid; p < 128*16; p += 256) {
            int row = p >> 4, f4 = p & 15;
            long base = ((long)(b*1024 + J0 + row))*3072 + n*64 + f4*4;
            float4 kv = *(const float4*)(g_heads + base + 1024);
            float4 vv = *(const float4*)(g_heads + base + 2048);
            float* dk = Ks + row*72 + f4*4;
            float* dv = Vs + row*72 + f4*4;
            dk[0]=f2tf32f(kv.x); dk[1]=f2tf32f(kv.y); dk[2]=f2tf32f(kv.z); dk[3]=f2tf32f(kv.w);
            dv[0]=f2tf32f(vv.x); dv[1]=f2tf32f(vv.y); dv[2]=f2tf32f(vv.z); dv[3]=f2tf32f(vv.w);
        }
        if (tid < 128) bks[tid] = g_biasK[((b*16 + n) << 10) + J0 + tid];
        { int t2 = tid; if (t2 < 256) brs[t2] = g_biasR[n*1152 + W0 + t2]; }
        __syncthreads();

        // ---- AC: warp-local 16 x 128 GEMM, K=64 ----
        float s[16][4];
#pragma unroll
        for (int ns = 0; ns < 16; ns++)
#pragma unroll
            for (int c = 0; c < 4; c++) s[ns][c] = 0.f;
#pragma unroll
        for (int ks = 0; ks < 64; ks += 8) {
            unsigned a[4];
            a[0] = __float_as_uint(q_s[(r0+grp  )*72 + ks+qid  ]);
            a[1] = __float_as_uint(q_s[(r0+grp+8)*72 + ks+qid  ]);
            a[2] = __float_as_uint(q_s[(r0+grp  )*72 + ks+qid+4]);
            a[3] = __float_as_uint(q_s[(r0+grp+8)*72 + ks+qid+4]);
#pragma unroll
            for (int ns = 0; ns < 16; ns++) {
                unsigned bb[2];
                int krow = ns*8 + grp;
                bb[0] = __float_as_uint(Ks[krow*72 + ks+qid  ]);
                bb[1] = __float_as_uint(Ks[krow*72 + ks+qid+4]);
                mma8(s[ns], a, bb);
            }
        }

        // ---- assemble S = (AC + BDband + bias_k + bias_r)*scale, mask ----
        const bool diag = (J0 == i0);
        float mt[2] = {-INFINITY, -INFINITY};
#pragma unroll
        for (int ns = 0; ns < 16; ns++) {
#pragma unroll
            for (int c = 0; c < 4; c++) {
                int li = grp + ((c >> 1) << 3);
                int jj = ns*8 + 2*qid + (c & 1);
                int cw = jj - li + 15;
                float v = (s[ns][c] + BDw[li*148 + cw] + bks[jj] + brs[off_w + cw]) * 0.125f;
                if (diag && jj > r0 + li) v = -1e30f;
                s[ns][c] = v;
                mt[c >> 1] = fmaxf(mt[c >> 1], v);
            }
        }
#pragma unroll
        for (int h = 0; h < 2; h++) {
            mt[h] = fmaxf(mt[h], __shfl_xor_sync(0xffffffffu, mt[h], 1));
            mt[h] = fmaxf(mt[h], __shfl_xor_sync(0xffffffffu, mt[h], 2));
        }
        float mnew[2], corr[2], sum[2];
#pragma unroll
        for (int h = 0; h < 2; h++) {
            mnew[h] = fmaxf(m_r[h], mt[h]);
            corr[h] = __expf(m_r[h] - mnew[h]);
            sum[h]  = 0.f;
        }
#pragma unroll
        for (int ns = 0; ns < 16; ns++) {
#pragma unroll
            for (int c = 0; c < 4; c++) {
                float p = __expf(s[ns][c] - mnew[c >> 1]);
                s[ns][c] = p;
                sum[c >> 1] += p;
            }
        }
#pragma unroll
        for (int h = 0; h < 2; h++) {
            sum[h] += __shfl_xor_sync(0xffffffffu, sum[h], 1);
            sum[h] += __shfl_xor_sync(0xffffffffu, sum[h], 2);
            l_r[h] = l_r[h]*corr[h] + sum[h];
            m_r[h] = mnew[h];
        }
#pragma unroll
        for (int ns = 0; ns < 8; ns++) {
            o[ns][0] *= corr[0]; o[ns][1] *= corr[0];
            o[ns][2] *= corr[1]; o[ns][3] *= corr[1];
        }

        // ---- write P (tf32) into warp-private slice, then AV ----
#pragma unroll
        for (int ns = 0; ns < 16; ns++) {
            int jj = ns*8 + 2*qid;
            BDw[ grp   *132 + jj] = f2tf32f(s[ns][0]); BDw[ grp   *132 + jj+1] = f2tf32f(s[ns][1]);
            BDw[(grp+8)*132 + jj] = f2tf32f(s[ns][2]); BDw[(grp+8)*132 + jj+1] = f2tf32f(s[ns][3]);
        }
        __syncwarp();
#pragma unroll
        for (int ks = 0; ks < 128; ks += 8) {
            unsigned a[4];
            a[0] = __float_as_uint(BDw[ grp   *132 + ks+qid  ]);
            a[1] = __float_as_uint(BDw[(grp+8)*132 + ks+qid  ]);
            a[2] = __float_as_uint(BDw[ grp   *132 + ks+qid+4]);
            a[3] = __float_as_uint(BDw[(grp+8)*132 + ks+qid+4]);
#pragma unroll
            for (int ns = 0; ns < 8; ns++) {
                unsigned bb[2];
                bb[0] = __float_as_uint(Vs[(ks+qid  )*72 + ns*8+grp]);
                bb[1] = __float_as_uint(Vs[(ks+qid+4)*72 + ns*8+grp]);
                mma8(o[ns], a, bb);
            }
        }
        __syncwarp();    // BDw/P reuse next iter is warp-local; Vs guarded by top-of-loop sync
    }

    // ---- epilogue: normalize + write av[b, i, n*64+d] ----
    float inv0 = 1.f / l_r[0];
    float inv1 = 1.f / l_r[1];
    int row0 = i0 + r0 + grp;
#pragma unroll
    for (int ns = 0; ns < 8; ns++) {
        int d = ns*8 + 2*qid;
        long base0 = ((long)(b*1024 + row0    ))*1024 + n*64 + d;
        long base1 = ((long)(b*1024 + row0 + 8))*1024 + n*64 + d;
        g_av[base0]   = o[ns][0]*inv0;
        g_av[base0+1] = o[ns][1]*inv0;
        g_av[base1]   = o[ns][2]*inv1;
        g_av[base1+1] = o[ns][3]*inv1;
    }
}

// ---------------- LayerNorm over rows of length D_ ----------------
__global__ void __launch_bounds__(256) ln_k(const float* __restrict__ x,
                                            const float* __restrict__ g,
                                            const float* __restrict__ bb,
                                            float* __restrict__ y)
{
    const int row = blockIdx.x;
    const int tid = threadIdx.x;
    const float* xr = x + (long)row*D_;
    float v[4], s = 0.f, s2 = 0.f;
#pragma unroll
    for (int t = 0; t < 4; t++) {
        v[t] = xr[tid + t*256];
        s += v[t]; s2 += v[t]*v[t];
    }
    __shared__ float r1[256], r2[256];
    r1[tid] = s; r2[tid] = s2; __syncthreads();
    for (int off = 128; off; off >>= 1) {
        if (tid < off) { r1[tid] += r1[tid+off]; r2[tid] += r2[tid+off]; }
        __syncthreads();
    }
    float mean = r1[0] * (1.f/D_);
    float var  = r2[0] * (1.f/D_) - mean*mean;
    float rstd = rsqrtf(var + 1e-5f);
#pragma unroll
    for (int t = 0; t < 4; t++) {
        int c = tid + t*256;
        y[(long)row*D_ + c] = (v[t] - mean)*rstd*g[c] + bb[c];
    }
}

// ---------------- host launch ----------------
static float* symaddr(const void* sym) {
    void* p = nullptr;
    cudaGetSymbolAddress(&p, sym);
    return (float*)p;
}

extern "C" void kernel_launch(void* const* d_in, const int* in_sizes, int n_in,
                              void* d_out, int out_size)
{
    const float* w       = (const float*)d_in[0];
    const float* r       = (const float*)d_in[1];
    // d_in[2] = attention_mask (causal) -- handled analytically
    const float* qkv_w   = (const float*)d_in[3];
    const float* r_w     = (const float*)d_in[4];
    const float* o_w     = (const float*)d_in[5];
    const float* r_w_bias= (const float*)d_in[6];
    const float* r_r_bias= (const float*)d_in[7];
    const float* ln1_g   = (const float*)d_in[8];
    const float* ln1_b   = (const float*)d_in[9];
    const float* ff_w1   = (const float*)d_in[10];
    const float* ff_b1   = (const float*)d_in[11];
    const float* ff_w2   = (const float*)d_in[12];
    const float* ff_b2   = (const float*)d_in[13];
    const float* ln2_g   = (const float*)d_in[14];
    const float* ln2_b   = (const float*)d_in[15];
    float* out = (float*)d_out;

    float* heads = symaddr(g_heads);
    float* rk    = symaddr(g_rk);
    float* av    = symaddr(g_av);
    float* tmp   = symaddr(g_tmp);
    float* out1  = symaddr(g_out1);
    float* ff1   = symaddr(g_ff1);

    static bool attr_set = false;
    if (!attr_set) {
        cudaFuncSetAttribute(flash_k, cudaFuncAttributeMaxDynamicSharedMemorySize,
                             FL_SMEM_FLOATS * 4);
        attr_set = true;
    }

    // 1) heads = w @ qkv_w^T   [4096,3072] k=1024
    gemm_tc<128,128,32,64,32><<<dim3(3072/128, 4096/128, 1), 256>>>(
        w, 1024, 0,0,  qkv_w, 1024, 0,0,  heads, 3072, 0,0,
        nullptr, nullptr, 1024, 0);

    // 2) rk = r @ r_w^T   [1024,1024] k=1024
    gemm_tc<128,128,32,64,32><<<dim3(1024/128, 1024/128, 1), 256>>>(
        r, 1024, 0,0,  r_w, 1024, 0,0,  rk, 1024, 0,0,
        nullptr, nullptr, 1024, 0);

    // 3) prep biases + head-major rk
    prep_biasK<<<(B_*NH_*Q_)/256, 256>>>(r_w_bias);
    prep_rk<<<(NH_*Q_)/256, 256>>>(r_r_bias);

    // 4) fused flash attention -> g_av
    flash_k<<<dim3(8, 16, 4), 256, FL_SMEM_FLOATS*4>>>();

    // 5) tmp = av @ o_w^T + w (residual)
    gemm_tc<128,128,32,64,32><<<dim3(8, 32, 1), 256>>>(
        av, 1024, 0,0,  o_w, 1024, 0,0,  tmp, 1024, 0,0,
        nullptr, w, 1024, 4);

    // 6) out1 = LN1(tmp)
    ln_k<<<M_, 256>>>(tmp, ln1_g, ln1_b, out1);

    // 7) ff1 = relu(out1 @ ff_w1^T + b1)   [4096,4096] k=1024
    gemm_tc<128,128,32,64,32><<<dim3(32, 32, 1), 256>>>(
        out1, 1024, 0,0,  ff_w1, 1024, 0,0,  ff1, 4096, 0,0,
        ff_b1, nullptr, 1024, 1|2);

    // 8) tmp = ff1 @ ff_w2^T + b2 + out1   [4096,1024] k=4096
    gemm_tc<128,128,32,64,32><<<dim3(8, 32, 1), 256>>>(
        ff1, 4096, 0,0,  ff_w2, 4096, 0,0,  tmp, 1024, 0,0,
        ff_b2, out1, 4096, 1|4);

    // 9) out = LN2(tmp)
    ln_k<<<M_, 256>>>(tmp, ln2_g, ln2_b, out);
}

// round 9
// speedup vs baseline: 2.5336x; 1.0940x over previous
#include <cuda_runtime.h>
#include <math.h>

// ---------------- problem constants ----------------
#define B_  4
#define Q_  1024
#define D_  1024
#define NH_ 16
#define DH_ 64
#define DI_ 4096
#define M_  (B_*Q_)      // 4096 rows

// ---------------- device scratch (static; no allocations) ----------------
__device__ float g_heads[(size_t)M_*3*D_];            // [b*Q+i, 3D]   48 MB
__device__ float g_rk   [(size_t)Q_*D_];              // [j, n*64+d]    4 MB
__device__ float g_rkB  [(size_t)NH_*1152*DH_];       // [n,c,d] pad rows 1024..1151 = 0
__device__ float g_biasK[(size_t)B_*NH_*Q_];          // rwb . k[b,n,j]
__device__ float g_biasR[(size_t)NH_*1152];           // rrb . rk[n,c]   (pad 0)
__device__ float g_av   [(size_t)M_*D_];              // 16 MB
__device__ float g_tmp  [(size_t)M_*D_];              // 16 MB
__device__ float g_out1 [(size_t)M_*D_];              // 16 MB
__device__ float g_ff1  [(size_t)M_*DI_];             // 64 MB

// ---------------- tf32 helpers ----------------
__device__ __forceinline__ unsigned f2tf32(float f) {
    unsigned u;
    asm("cvt.rna.tf32.f32 %0, %1;" : "=r"(u) : "f"(f));
    return u;
}
__device__ __forceinline__ float f2tf32f(float f) { return __uint_as_float(f2tf32(f)); }

__device__ __forceinline__ void mma8(float* d, const unsigned* a, const unsigned* b) {
    asm volatile(
        "mma.sync.aligned.m16n8k8.row.col.f32.tf32.tf32.f32 "
        "{%0,%1,%2,%3}, {%4,%5,%6,%7}, {%8,%9}, {%0,%1,%2,%3};"
        : "+f"(d[0]), "+f"(d[1]), "+f"(d[2]), "+f"(d[3])
        : "r"(a[0]), "r"(a[1]), "r"(a[2]), "r"(a[3]),
          "r"(b[0]), "r"(b[1]));
}

// ---------------- pipelined tensor-core GEMM:  C = A @ B^T (tf32/fp32) -----
// 2-stage smem double buffer + register prefetch; ONE syncthreads per BK tile.
// mode bits: 1 = +bias[col], 2 = relu, 4 = +resid
template<int BM,int BN,int BK,int WM,int WN>
__global__ void __launch_bounds__(256, 2)
gemm_tc(const float* __restrict__ A, int lda, long aHi, long aLo,
        const float* __restrict__ B, int ldb, long bHi, long bLo,
        float*       __restrict__ C, int ldc, long cHi, long cLo,
        const float* __restrict__ bias,
        const float* __restrict__ resid,
        int K, int mode)
{
    constexpr int MS = WM/16;
    constexpr int NS = WN/8;
    constexpr int WROWS = BM/WM;
    constexpr int AL = BM*BK/(4*256);     // float4 loads per thread (A)
    constexpr int BL = BN*BK/(4*256);     // float4 loads per thread (B)
    static_assert((BM/WM)*(BN/WN) == 8, "8 warps");

    __shared__ unsigned As[2][BK][BM+4];
    __shared__ unsigned Bs[2][BK][BN+4];

    const int z    = blockIdx.z;
    const long aOff = (long)(z/16)*aHi + (long)(z%16)*aLo;
    const long bOff = (long)(z/16)*bHi + (long)(z%16)*bLo;
    const long cOff = (long)(z/16)*cHi + (long)(z%16)*cLo;

    const int m0 = blockIdx.y * BM;
    const int n0 = blockIdx.x * BN;
    const int tid  = threadIdx.x;
    const int wid  = tid >> 5;
    const int lane = tid & 31;
    const int wm = (wid % WROWS) * WM;
    const int wn = (wid / WROWS) * WN;
    const int grp = lane >> 2;
    const int qid = lane & 3;

    const float* Ab = A + aOff + (long)m0 * lda;
    const float* Bb = B + bOff + (long)n0 * ldb;

    // fixed per-thread load slots
    int am[AL], ak[AL], bm[BL], bk[BL];
#pragma unroll
    for (int l = 0; l < AL; l++) { int s = tid + l*256; am[l] = s/(BK/4); ak[l] = (s%(BK/4))*4; }
#pragma unroll
    for (int l = 0; l < BL; l++) { int s = tid + l*256; bm[l] = s/(BK/4); bk[l] = (s%(BK/4))*4; }

    float acc[MS][NS][4];
#pragma unroll
    for (int i = 0; i < MS; i++)
#pragma unroll
        for (int j = 0; j < NS; j++)
#pragma unroll
            for (int c = 0; c < 4; c++) acc[i][j][c] = 0.f;

    float4 pa[AL], pb[BL];

    // prologue: fetch tile 0, stage into buffer 0
#pragma unroll
    for (int l = 0; l < AL; l++) pa[l] = *(const float4*)(Ab + (long)am[l]*lda + ak[l]);
#pragma unroll
    for (int l = 0; l < BL; l++) pb[l] = *(const float4*)(Bb + (long)bm[l]*ldb + bk[l]);
#pragma unroll
    for (int l = 0; l < AL; l++) {
        As[0][ak[l]+0][am[l]] = f2tf32(pa[l].x); As[0][ak[l]+1][am[l]] = f2tf32(pa[l].y);
        As[0][ak[l]+2][am[l]] = f2tf32(pa[l].z); As[0][ak[l]+3][am[l]] = f2tf32(pa[l].w);
    }
#pragma unroll
    for (int l = 0; l < BL; l++) {
        Bs[0][bk[l]+0][bm[l]] = f2tf32(pb[l].x); Bs[0][bk[l]+1][bm[l]] = f2tf32(pb[l].y);
        Bs[0][bk[l]+2][bm[l]] = f2tf32(pb[l].z); Bs[0][bk[l]+3][bm[l]] = f2tf32(pb[l].w);
    }
    __syncthreads();

    int cur = 0;
    for (int k0 = 0; k0 < K; k0 += BK) {
        const bool more = (k0 + BK) < K;
        // prefetch next tile into registers (overlaps with MMA below)
        if (more) {
#pragma unroll
            for (int l = 0; l < AL; l++)
                pa[l] = *(const float4*)(Ab + (long)am[l]*lda + k0 + BK + ak[l]);
#pragma unroll
            for (int l = 0; l < BL; l++)
                pb[l] = *(const float4*)(Bb + (long)bm[l]*ldb + k0 + BK + bk[l]);
        }

        // compute current stage
#pragma unroll
        for (int ks = 0; ks < BK; ks += 8) {
            unsigned a[MS][4], b[NS][2];
#pragma unroll
            for (int ms = 0; ms < MS; ms++) {
                int m = wm + ms*16 + grp;
                a[ms][0] = As[cur][ks+qid  ][m];
                a[ms][1] = As[cur][ks+qid  ][m+8];
                a[ms][2] = As[cur][ks+qid+4][m];
                a[ms][3] = As[cur][ks+qid+4][m+8];
            }
#pragma unroll
            for (int ns = 0; ns < NS; ns++) {
                int n = wn + ns*8 + grp;
                b[ns][0] = Bs[cur][ks+qid  ][n];
                b[ns][1] = Bs[cur][ks+qid+4][n];
            }
#pragma unroll
            for (int ms = 0; ms < MS; ms++)
#pragma unroll
                for (int ns = 0; ns < NS; ns++)
                    mma8(acc[ms][ns], a[ms], b[ns]);
        }

        // stage next tile into the other buffer (safe: last read of it was
        // fenced by the barrier at the end of the previous iteration)
        if (more) {
            int nxt = cur ^ 1;
#pragma unroll
            for (int l = 0; l < AL; l++) {
                As[nxt][ak[l]+0][am[l]] = f2tf32(pa[l].x); As[nxt][ak[l]+1][am[l]] = f2tf32(pa[l].y);
                As[nxt][ak[l]+2][am[l]] = f2tf32(pa[l].z); As[nxt][ak[l]+3][am[l]] = f2tf32(pa[l].w);
            }
#pragma unroll
            for (int l = 0; l < BL; l++) {
                Bs[nxt][bk[l]+0][bm[l]] = f2tf32(pb[l].x); Bs[nxt][bk[l]+1][bm[l]] = f2tf32(pb[l].y);
                Bs[nxt][bk[l]+2][bm[l]] = f2tf32(pb[l].z); Bs[nxt][bk[l]+3][bm[l]] = f2tf32(pb[l].w);
            }
        }
        __syncthreads();
        cur ^= 1;
    }

    // epilogue (float2 stores; col = even, 8B aligned)
#pragma unroll
    for (int ms = 0; ms < MS; ms++) {
#pragma unroll
        for (int ns = 0; ns < NS; ns++) {
#pragma unroll
            for (int half = 0; half < 2; half++) {
                long row = m0 + wm + ms*16 + grp + half*8;
                int  col = n0 + wn + ns*8 + 2*qid;
                float v0 = acc[ms][ns][half*2 + 0];
                float v1 = acc[ms][ns][half*2 + 1];
                if (mode & 1) { v0 += bias[col]; v1 += bias[col+1]; }
                if (mode & 2) { v0 = fmaxf(v0, 0.f); v1 = fmaxf(v1, 0.f); }
                long cbase = cOff + row*ldc + col;
                if (mode & 4) {
                    float2 rr = *(const float2*)(resid + cbase);
                    v0 += rr.x; v1 += rr.y;
                }
                float2 vv; vv.x = v0; vv.y = v1;
                *(float2*)(C + cbase) = vv;
            }
        }
    }
}

// ---------------- prep: bias_k[b,n,j] = rwb[n] . K[b,n,j] ----------------
__global__ void prep_biasK(const float* __restrict__ rwb)
{
    int idx = blockIdx.x*256 + threadIdx.x;     // (b*16+n)*1024 + j
    int j = idx & 1023; int n = (idx >> 10) & 15; int b = idx >> 14;
    const float* kk = g_heads + ((long)(b*1024 + j))*3072 + 1024 + n*64;
    const float* wv = rwb + n*64;
    float s = 0.f;
#pragma unroll
    for (int d = 0; d < 64; d++) s += wv[d]*kk[d];
    g_biasK[idx] = s;
}

// ---------------- prep: rkB[n,c,d] + bias_r[n,c] ----------------
__global__ void prep_rk(const float* __restrict__ rrb)
{
    int idx = blockIdx.x*256 + threadIdx.x;     // n*1024 + c
    int c = idx & 1023; int n = idx >> 10;
    const float* src = g_rk + (long)c*1024 + n*64;
    const float* wv  = rrb + n*64;
    float* dst = g_rkB + ((long)n*1152 + c)*64;
    float s = 0.f;
#pragma unroll
    for (int d = 0; d < 64; d++) { float v = src[d]; dst[d] = v; s += wv[d]*v; }
    g_biasR[n*1152 + c] = s;
}

// ---------------- fused flash attention (AC + banded BD + softmax + AV) ----
// grid (8 i-tiles, 16 heads, 4 batch); 256 threads = 8 warps, warp w owns
// rows [w*16, w*16+16) of the 128-row Q tile. tf32 MMA throughout.
#define FL_SMEM_FLOATS 46976

__global__ void __launch_bounds__(256)
flash_k()
{
    extern __shared__ float sm[];
    float* q_s = sm;                 // [128][72]
    float* rA  = sm + 9216;          // rks [256][72]
    float* Ks  = rA;                 // [128][72]
    float* Vs  = rA + 9216;          // [128][72]
    float* BDb = sm + 27648;         // 8 * 2368
    float* bks = sm + 46592;
    float* brs = sm + 46720;

    const int it = blockIdx.x, n = blockIdx.y, b = blockIdx.z;
    const int i0 = it * 128;
    const int tid = threadIdx.x, wid = tid >> 5, lane = tid & 31;
    const int grp = lane >> 2, qid = lane & 3;
    const int r0 = wid * 16;
    const int off_w = 112 - r0;
    float* BDw = BDb + wid*2368;     // warp-private: BD band [16][148] / P [16][132]

    // load q tile (fp32 -> tf32)
    for (int p = tid; p < 128*16; p += 256) {
        int row = p >> 4, f4 = p & 15;
        float4 v = *(const float4*)(g_heads + ((long)(b*1024 + i0 + row))*3072 + n*64 + f4*4);
        float* dst = q_s + row*72 + f4*4;
        dst[0]=f2tf32f(v.x); dst[1]=f2tf32f(v.y); dst[2]=f2tf32f(v.z); dst[3]=f2tf32f(v.w);
    }

    float o[8][4];
#pragma unroll
    for (int ns = 0; ns < 8; ns++)
#pragma unroll
        for (int c = 0; c < 4; c++) o[ns][c] = 0.f;
    float m_r[2] = {-INFINITY, -INFINITY};
    float l_r[2] = {0.f, 0.f};

    for (int J0 = 0; J0 <= i0; J0 += 128) {
        const int W0 = J0 - i0 + 896;          // rk window start (>= 0)

        // ---- load rk window [256][64] ----
        __syncthreads();                        // protect Vs of previous iter
        for (int p = tid; p < 256*16; p += 256) {
            int row = p >> 4, f4 = p & 15;
            float4 v = *(const float4*)(g_rkB + ((long)n*1152 + W0 + row)*64 + f4*4);
            float* dst = rA + row*72 + f4*4;
            dst[0]=f2tf32f(v.x); dst[1]=f2tf32f(v.y); dst[2]=f2tf32f(v.z); dst[3]=f2tf32f(v.w);
        }
        __syncthreads();

        // ---- BD band: warp-local 16 x 144 GEMM, K=64 ----
        {
            float bd[18][4];
#pragma unroll
            for (int ns = 0; ns < 18; ns++)
#pragma unroll
                for (int c = 0; c < 4; c++) bd[ns][c] = 0.f;
#pragma unroll
            for (int ks = 0; ks < 64; ks += 8) {
                unsigned a[4];
                a[0] = __float_as_uint(q_s[(r0+grp  )*72 + ks+qid  ]);
                a[1] = __float_as_uint(q_s[(r0+grp+8)*72 + ks+qid  ]);
                a[2] = __float_as_uint(q_s[(r0+grp  )*72 + ks+qid+4]);
                a[3] = __float_as_uint(q_s[(r0+grp+8)*72 + ks+qid+4]);
#pragma unroll
                for (int ns = 0; ns < 18; ns++) {
                    unsigned bb[2];
                    int rrow = off_w + ns*8 + grp;
                    bb[0] = __float_as_uint(rA[rrow*72 + ks+qid  ]);
                    bb[1] = __float_as_uint(rA[rrow*72 + ks+qid+4]);
                    mma8(bd[ns], a, bb);
                }
            }
#pragma unroll
            for (int ns = 0; ns < 18; ns++) {
                int cw = ns*8 + 2*qid;
                BDw[ grp   *148 + cw] = bd[ns][0]; BDw[ grp   *148 + cw+1] = bd[ns][1];
                BDw[(grp+8)*148 + cw] = bd[ns][2]; BDw[(grp+8)*148 + cw+1] = bd[ns][3];
            }
        }
        __syncthreads();

        // ---- load K, V tiles + bias windows (overwrites rk window) ----
        for (int p = tid; p < 128*16; p += 256) {
            int row = p >> 4, f4 = p & 15;
            long base = ((long)(b*1024 + J0 + row))*3072 + n*64 + f4*4;
            float4 kv = *(const float4*)(g_heads + base + 1024);
            float4 vv = *(const float4*)(g_heads + base + 2048);
            float* dk = Ks + row*72 + f4*4;
            float* dv = Vs + row*72 + f4*4;
            dk[0]=f2tf32f(kv.x); dk[1]=f2tf32f(kv.y); dk[2]=f2tf32f(kv.z); dk[3]=f2tf32f(kv.w);
            dv[0]=f2tf32f(vv.x); dv[1]=f2tf32f(vv.y); dv[2]=f2tf32f(vv.z); dv[3]=f2tf32f(vv.w);
        }
        if (tid < 128) bks[tid] = g_biasK[((b*16 + n) << 10) + J0 + tid];
        { int t2 = tid; if (t2 < 256) brs[t2] = g_biasR[n*1152 + W0 + t2]; }
        __syncthreads();

        // ---- AC: warp-local 16 x 128 GEMM, K=64 ----
        float s[16][4];
#pragma unroll
        for (int ns = 0; ns < 16; ns++)
#pragma unroll
            for (int c = 0; c < 4; c++) s[ns][c] = 0.f;
#pragma unroll
        for (int ks = 0; ks < 64; ks += 8) {
            unsigned a[4];
            a[0] = __float_as_uint(q_s[(r0+grp  )*72 + ks+qid  ]);
            a[1] = __float_as_uint(q_s[(r0+grp+8)*72 + ks+qid  ]);
            a[2] = __float_as_uint(q_s[(r0+grp  )*72 + ks+qid+4]);
            a[3] = __float_as_uint(q_s[(r0+grp+8)*72 + ks+qid+4]);
#pragma unroll
            for (int ns = 0; ns < 16; ns++) {
                unsigned bb[2];
                int krow = ns*8 + grp;
                bb[0] = __float_as_uint(Ks[krow*72 + ks+qid  ]);
                bb[1] = __float_as_uint(Ks[krow*72 + ks+qid+4]);
                mma8(s[ns], a, bb);
            }
        }

        // ---- assemble S = (AC + BDband + bias_k + bias_r)*scale, mask ----
        const bool diag = (J0 == i0);
        float mt[2] = {-INFINITY, -INFINITY};
#pragma unroll
        for (int ns = 0; ns < 16; ns++) {
#pragma unroll
            for (int c = 0; c < 4; c++) {
                int li = grp + ((c >> 1) << 3);
                int jj = ns*8 + 2*qid + (c & 1);
                int cw = jj - li + 15;
                float v = (s[ns][c] + BDw[li*148 + cw] + bks[jj] + brs[off_w + cw]) * 0.125f;
                if (diag && jj > r0 + li) v = -1e30f;
                s[ns][c] = v;
                mt[c >> 1] = fmaxf(mt[c >> 1], v);
            }
        }
#pragma unroll
        for (int h = 0; h < 2; h++) {
            mt[h] = fmaxf(mt[h], __shfl_xor_sync(0xffffffffu, mt[h], 1));
            mt[h] = fmaxf(mt[h], __shfl_xor_sync(0xffffffffu, mt[h], 2));
        }
        float mnew[2], corr[2], sum[2];
#pragma unroll
        for (int h = 0; h < 2; h++) {
            mnew[h] = fmaxf(m_r[h], mt[h]);
            corr[h] = __expf(m_r[h] - mnew[h]);
            sum[h]  = 0.f;
        }
#pragma unroll
        for (int ns = 0; ns < 16; ns++) {
#pragma unroll
            for (int c = 0; c < 4; c++) {
                float p = __expf(s[ns][c] - mnew[c >> 1]);
                s[ns][c] = p;
                sum[c >> 1] += p;
            }
        }
#pragma unroll
        for (int h = 0; h < 2; h++) {
            sum[h] += __shfl_xor_sync(0xffffffffu, sum[h], 1);
            sum[h] += __shfl_xor_sync(0xffffffffu, sum[h], 2);
            l_r[h] = l_r[h]*corr[h] + sum[h];
            m_r[h] = mnew[h];
        }
#pragma unroll
        for (int ns = 0; ns < 8; ns++) {
            o[ns][0] *= corr[0]; o[ns][1] *= corr[0];
            o[ns][2] *= corr[1]; o[ns][3] *= corr[1];
        }

        // ---- write P (tf32) into warp-private slice, then AV ----
#pragma unroll
        for (int ns = 0; ns < 16; ns++) {
            int jj = ns*8 + 2*qid;
            BDw[ grp   *132 + jj] = f2tf32f(s[ns][0]); BDw[ grp   *132 + jj+1] = f2tf32f(s[ns][1]);
            BDw[(grp+8)*132 + jj] = f2tf32f(s[ns][2]); BDw[(grp+8)*132 + jj+1] = f2tf32f(s[ns][3]);
        }
        __syncwarp();
#pragma unroll
        for (int ks = 0; ks < 128; ks += 8) {
            unsigned a[4];
            a[0] = __float_as_uint(BDw[ grp   *132 + ks+qid  ]);
            a[1] = __float_as_uint(BDw[(grp+8)*132 + ks+qid  ]);
            a[2] = __float_as_uint(BDw[ grp   *132 + ks+qid+4]);
            a[3] = __float_as_uint(BDw[(grp+8)*132 + ks+qid+4]);
#pragma unroll
            for (int ns = 0; ns < 8; ns++) {
                unsigned bb[2];
                bb[0] = __float_as_uint(Vs[(ks+qid  )*72 + ns*8+grp]);
                bb[1] = __float_as_uint(Vs[(ks+qid+4)*72 + ns*8+grp]);
                mma8(o[ns], a, bb);
            }
        }
        __syncwarp();
    }

    // ---- epilogue: normalize + write av[b, i, n*64+d] ----
    float inv0 = 1.f / l_r[0];
    float inv1 = 1.f / l_r[1];
    int row0 = i0 + r0 + grp;
#pragma unroll
    for (int ns = 0; ns < 8; ns++) {
        int d = ns*8 + 2*qid;
        long base0 = ((long)(b*1024 + row0    ))*1024 + n*64 + d;
        long base1 = ((long)(b*1024 + row0 + 8))*1024 + n*64 + d;
        g_av[base0]   = o[ns][0]*inv0;
        g_av[base0+1] = o[ns][1]*inv0;
        g_av[base1]   = o[ns][2]*inv1;
        g_av[base1+1] = o[ns][3]*inv1;
    }
}

// ---------------- LayerNorm over rows of length D_ ----------------
__global__ void __launch_bounds__(256) ln_k(const float* __restrict__ x,
                                            const float* __restrict__ g,
                                            const float* __restrict__ bb,
                                            float* __restrict__ y)
{
    const int row = blockIdx.x;
    const int tid = threadIdx.x;
    const float* xr = x + (long)row*D_;
    float v[4], s = 0.f, s2 = 0.f;
#pragma unroll
    for (int t = 0; t < 4; t++) {
        v[t] = xr[tid + t*256];
        s += v[t]; s2 += v[t]*v[t];
    }
    __shared__ float r1[256], r2[256];
    r1[tid] = s; r2[tid] = s2; __syncthreads();
    for (int off = 128; off; off >>= 1) {
        if (tid < off) { r1[tid] += r1[tid+off]; r2[tid] += r2[tid+off]; }
        __syncthreads();
    }
    float mean = r1[0] * (1.f/D_);
    float var  = r2[0] * (1.f/D_) - mean*mean;
    float rstd = rsqrtf(var + 1e-5f);
#pragma unroll
    for (int t = 0; t < 4; t++) {
        int c = tid + t*256;
        y[(long)row*D_ + c] = (v[t] - mean)*rstd*g[c] + bb[c];
    }
}

// ---------------- host launch ----------------
static float* symaddr(const void* sym) {
    void* p = nullptr;
    cudaGetSymbolAddress(&p, sym);
    return (float*)p;
}

extern "C" void kernel_launch(void* const* d_in, const int* in_sizes, int n_in,
                              void* d_out, int out_size)
{
    const float* w       = (const float*)d_in[0];
    const float* r       = (const float*)d_in[1];
    // d_in[2] = attention_mask (causal) -- handled analytically
    const float* qkv_w   = (const float*)d_in[3];
    const float* r_w     = (const float*)d_in[4];
    const float* o_w     = (const float*)d_in[5];
    const float* r_w_bias= (const float*)d_in[6];
    const float* r_r_bias= (const float*)d_in[7];
    const float* ln1_g   = (const float*)d_in[8];
    const float* ln1_b   = (const float*)d_in[9];
    const float* ff_w1   = (const float*)d_in[10];
    const float* ff_b1   = (const float*)d_in[11];
    const float* ff_w2   = (const float*)d_in[12];
    const float* ff_b2   = (const float*)d_in[13];
    const float* ln2_g   = (const float*)d_in[14];
    const float* ln2_b   = (const float*)d_in[15];
    float* out = (float*)d_out;

    float* heads = symaddr(g_heads);
    float* rk    = symaddr(g_rk);
    float* av    = symaddr(g_av);
    float* tmp   = symaddr(g_tmp);
    float* out1  = symaddr(g_out1);
    float* ff1   = symaddr(g_ff1);

    static bool attr_set = false;
    if (!attr_set) {
        cudaFuncSetAttribute(flash_k, cudaFuncAttributeMaxDynamicSharedMemorySize,
                             FL_SMEM_FLOATS * 4);
        attr_set = true;
    }

    // 1) heads = w @ qkv_w^T   [4096,3072] k=1024
    gemm_tc<128,128,16,64,32><<<dim3(3072/128, 4096/128, 1), 256>>>(
        w, 1024, 0,0,  qkv_w, 1024, 0,0,  heads, 3072, 0,0,
        nullptr, nullptr, 1024, 0);

    // 2) rk = r @ r_w^T   [1024,1024] k=1024
    gemm_tc<128,128,16,64,32><<<dim3(1024/128, 1024/128, 1), 256>>>(
        r, 1024, 0,0,  r_w, 1024, 0,0,  rk, 1024, 0,0,
        nullptr, nullptr, 1024, 0);

    // 3) prep biases + head-major rk
    prep_biasK<<<(B_*NH_*Q_)/256, 256>>>(r_w_bias);
    prep_rk<<<(NH_*Q_)/256, 256>>>(r_r_bias);

    // 4) fused flash attention -> g_av
    flash_k<<<dim3(8, 16, 4), 256, FL_SMEM_FLOATS*4>>>();

    // 5) tmp = av @ o_w^T + w (residual)
    gemm_tc<128,128,16,64,32><<<dim3(8, 32, 1), 256>>>(
        av, 1024, 0,0,  o_w, 1024, 0,0,  tmp, 1024, 0,0,
        nullptr, w, 1024, 4);

    // 6) out1 = LN1(tmp)
    ln_k<<<M_, 256>>>(tmp, ln1_g, ln1_b, out1);

    // 7) ff1 = relu(out1 @ ff_w1^T + b1)   [4096,4096] k=1024
    gemm_tc<128,128,16,64,32><<<dim3(32, 32, 1), 256>>>(
        out1, 1024, 0,0,  ff_w1, 1024, 0,0,  ff1, 4096, 0,0,
        ff_b1, nullptr, 1024, 1|2);

    // 8) tmp = ff1 @ ff_w2^T + b2 + out1   [4096,1024] k=4096
    gemm_tc<128,128,16,64,32><<<dim3(8, 32, 1), 256>>>(
        ff1, 4096, 0,0,  ff_w2, 4096, 0,0,  tmp, 1024, 0,0,
        ff_b2, out1, 4096, 1|4);

    // 9) out = LN2(tmp)
    ln_k<<<M_, 256>>>(tmp, ln2_g, ln2_b, out);
}